// round 17
// baseline (speedup 1.0000x reference)
#include <cuda_runtime.h>
#include <stdint.h>

// TDGSPooling2d: gumbel-softmax hard pooling over 2x2 patches (forward = argmax).
// out[b,c,ho,wo] = x_patch[argmax_k(x_patch[k]/temp[c,ho,wo] + g_k)]
// Noise: JAX partitionable threefry: bits[i] = o0^o1,
//   (o0,o1) = threefry2x32(key=(0,42), counter=(0,i))
//
// R17: persistent grid-stride, exactly ONE wave. 1184 blocks x 256 threads
// (32 regs -> 8 blocks/SM x 148 SMs = 1184 resident). Eliminates ~10 wave
// transitions (~2360 cyc each) + partial-wave tail that the per-warp levers
// (occupancy R12, ILP R14, pipe balance R16) could not touch.
// Hash + gumbel identical to R16 -> rel_err exactly 6.03701e-4.

#define QC 12845056u   // x element stride AND counter stride per quarter (=4*QO)
#define QO 3211264u    // output element stride per batch-quarter (8*401408)
#define NP 3211264u    // quad-thread work items (b<8 x 128 x 56 x 56)

// add on the FMA pipe: a*one + b, one==1 but unprovable by ptxas
__device__ __forceinline__ uint32_t addf(uint32_t a, uint32_t b, uint32_t one) {
    uint32_t r;
    asm("mad.lo.u32 %0, %1, %2, %3;" : "=r"(r) : "r"(a), "r"(one), "r"(b));
    return r;
}

// ---------- threefry2x32, key=(0,42), counter (0,c1), return o0^o1 ----------
// ks0 = 0, ks1 = 42, ks2 = 0x1BD11BDA ^ 0 ^ 42 = 0x1BD11BF0
// Rounds: x0 += x1 (addf); x1 = rotl(x1,r) ^ x0  (SHF + LOP3, the alu core).
// ALL key injections via addf -> zero alu adds in the hash.
__device__ __forceinline__ uint32_t tf_xor_0_42(uint32_t c1, uint32_t one) {
    const uint32_t ks1 = 42u;
    const uint32_t ks2 = 0x1BD11BF0u;
    uint32_t x1 = addf(c1, ks1, one);
    uint32_t x0 = x1;                 // round-1 add with x0 = c0+ks0 = 0
    x1 = __funnelshift_l(x1, x1, 13) ^ x0;
#define R(r) { x0 = addf(x1, x0, one); x1 = __funnelshift_l(x1, x1, (r)) ^ x0; }
    R(15) R(26) R(6)                                    // rounds 2-4
    x0 = addf(x0, ks1, one);  x1 = addf(x1, ks2 + 1u, one);   // inject 1
    R(17) R(29) R(16) R(24)                             // rounds 5-8
    x0 = addf(x0, ks2, one);  x1 = addf(x1, 2u, one);         // inject 2
    R(13) R(15) R(26) R(6)                              // rounds 9-12
    /* x0 += ks0 (=0) */      x1 = addf(x1, ks1 + 3u, one);   // inject 3
    R(17) R(29) R(16) R(24)                             // rounds 13-16
    x0 = addf(x0, ks1, one);  x1 = addf(x1, ks2 + 4u, one);   // inject 4
    R(13) R(15) R(26) R(6)                              // rounds 17-20
#undef R
    x0 = addf(x0, ks2, one);  x1 = addf(x1, 5u, one);         // final inject
    return x0 ^ x1;
}

// ---------- gumbel score term, log-domain, no bit-prep (verified R15) -----
// L = log2(-log2(u')) with u' = r * 2^-32:
//   bf = (float)r; nl2 = 32 - __log2f(bf); L = __log2f(nl2)
// r=0: L=+inf -> w=-inf, never wins (reference's clamped lane also never wins).
__device__ __forceinline__ float log2_negl2_u(uint32_t r) {
    float bf = (float)r;
    float nl2 = 32.0f - __log2f(bf);
    return __log2f(nl2);
}

__device__ __forceinline__ float argmax_pick(float2 v0, float2 v1, float rt2,
                                             uint32_t r0, uint32_t r1,
                                             uint32_t r2, uint32_t r3) {
    float wb = fmaf(v0.x, rt2, -log2_negl2_u(r0));
    float xb = v0.x;
    float w;
    w = fmaf(v0.y, rt2, -log2_negl2_u(r1)); if (w > wb) { wb = w; xb = v0.y; }
    w = fmaf(v1.x, rt2, -log2_negl2_u(r2)); if (w > wb) { wb = w; xb = v1.x; }
    w = fmaf(v1.y, rt2, -log2_negl2_u(r3)); if (w > wb) { wb = w; xb = v1.y; }
    return xb;
}

__global__ __launch_bounds__(256, 8)
void tdgs_pool_kernel(const float* __restrict__ x,
                      const float* __restrict__ temp,
                      float* __restrict__ out) {
    uint32_t one = gridDim.y;                       // == 1, opaque to ptxas
    unsigned stride = gridDim.x * 256u;             // = 303,104

    for (unsigned p = blockIdx.x * 256u + threadIdx.x; p < NP; p += stride) {
        unsigned t2 = p / 3136u;                    // b*128 + c, b < 8
        unsigned hw = p - t2 * 3136u;               // ho*56 + wo
        unsigned ho = hw / 56u;
        unsigned c  = t2 & 127u;

        // temperature: relu + 0.1; rt2 = (1/t)/ln2 shared by all 4 outputs
        float T  = temp[c * 3136u + hw];
        float tt = fmaxf(T, 0.0f) + 0.1f;
        float rt2 = __frcp_rn(tt) * 1.44269504088896340736f;

        // xoff = t2*12544 + 2*ho*112 + 2*wo = t2*12544 + 2*hw + 112*ho
        unsigned xoff = t2 * 12544u + 2u * hw + 112u * ho;
        unsigned base = p * 4u;

        // Hoisted patch loads: memory latency decoupled from compute.
        float2 v0[4], v1[4];
        #pragma unroll
        for (unsigned q = 0; q < 4; q++) {
            unsigned xo = xoff + q * QC;
            v0[q] = *reinterpret_cast<const float2*>(x + xo);
            v1[q] = *reinterpret_cast<const float2*>(x + xo + 112u);
        }

        #pragma unroll
        for (unsigned q = 0; q < 4; q++) {
            unsigned cb = base + q * QC;          // counter stride = 4*QO = QC
            uint32_t r0 = tf_xor_0_42(cb + 0u, one);
            uint32_t r1 = tf_xor_0_42(cb + 1u, one);
            uint32_t r2 = tf_xor_0_42(cb + 2u, one);
            uint32_t r3 = tf_xor_0_42(cb + 3u, one);
            out[p + q * QO] = argmax_pick(v0[q], v1[q], rt2, r0, r1, r2, r3);
        }
    }
}

extern "C" void kernel_launch(void* const* d_in, const int* in_sizes, int n_in,
                              void* d_out, int out_size) {
    const float* x    = (const float*)d_in[0];   // (32,128,112,112) fp32
    const float* temp = (const float*)d_in[1];   // (128,56,56) fp32
    float* out        = (float*)d_out;           // (32,128,56,56) fp32

    // One resident wave: 148 SMs x 8 blocks/SM (32 regs, 256 thr) = 1184.
    tdgs_pool_kernel<<<dim3(1184, 1, 1), 256>>>(x, temp, out);
}